// round 2
// baseline (speedup 1.0000x reference)
#include <cuda_runtime.h>
#include <math.h>

// ---------------- problem constants ----------------
#define BSZ   32
#define HW    56
#define CDIM  192
#define NHEAD 6
#define HD    32
#define WSZ   7
#define NTOK  49          // 7*7
#define NWIN  64          // 8*8 windows per image
#define TTOT  (BSZ*HW*HW) // 100352 tokens
#define HID   768

// scratch (bss, no allocation)
__device__ float g_xattn[TTOT * CDIM];   // attention output (pre-LN2) = residual for MLP
__device__ float g_xn2  [TTOT * CDIM];   // LN2(x_attn)
__device__ float g_h    [TTOT * HID];    // gelu(xn2@w1+b1)

// ---------------- attention kernel smem layout (floats) ----------------
// region A: xn (49*192=9408) -> scores_t [6][49][52] (15288) -> yb (9408)
#define A_OFF    0
#define A_SIZE   15296
#define QKV_OFF  15296            // 49*576 = 28224
#define MU_OFF   (QKV_OFF + 28224)
#define RS_OFF   (MU_OFF + 56)
#define SMEM_FLOATS (RS_OFF + 56)
#define SMEM_BYTES  (SMEM_FLOATS * 4)

__global__ void __launch_bounds__(192)
attn_kernel(const float* __restrict__ x,
            const float* __restrict__ qkv_w, const float* __restrict__ qkv_b,
            const float* __restrict__ proj_w, const float* __restrict__ proj_b,
            const float* __restrict__ g1, const float* __restrict__ be1,
            const float* __restrict__ g2, const float* __restrict__ be2)
{
    extern __shared__ float sm[];
    float* xn  = sm + A_OFF;     // reused as scores_t, then yb
    float* qkv = sm + QKV_OFF;
    float* mu  = sm + MU_OFF;
    float* rs  = sm + RS_OFF;

    const int tid = threadIdx.x;
    const int blk = blockIdx.x;
    const int b   = blk >> 6;
    const int w   = blk & 63;
    const int wr  = w >> 3;
    const int wc  = w & 7;

    const float* xb = x + (size_t)b * (HW*HW) * CDIM;

    // ---- gather shifted window: column tid of all 49 rows ----
    #pragma unroll 1
    for (int m = 0; m < NTOK; m++) {
        int ti = m / 7, tj = m - ti * 7;
        int sr = wr*7 + ti + 3; if (sr >= HW) sr -= HW;
        int sc = wc*7 + tj + 3; if (sc >= HW) sc -= HW;
        xn[m*CDIM + tid] = xb[(size_t)(sr*HW + sc)*CDIM + tid];
    }
    __syncthreads();

    // ---- LN1 stats: one thread per row, lane-staggered to dodge bank conflicts ----
    if (tid < NTOK) {
        const float* r = xn + tid*CDIM;
        int off = (tid & 31) * 6;
        float s = 0.f, s2 = 0.f;
        for (int kk = 0; kk < CDIM; kk++) {
            int k = kk + off; if (k >= CDIM) k -= CDIM;
            float v = r[k]; s += v; s2 += v*v;
        }
        float m_ = s * (1.f/CDIM);
        float v_ = s2 * (1.f/CDIM) - m_*m_;
        mu[tid] = m_;
        rs[tid] = rsqrtf(v_ + 1e-5f);
    }
    __syncthreads();
    {
        float gc = g1[tid], bc = be1[tid];
        #pragma unroll
        for (int m = 0; m < NTOK; m++)
            xn[m*CDIM + tid] = (xn[m*CDIM + tid] - mu[m]) * rs[m] * gc + bc;
    }
    __syncthreads();

    // ---- QKV: [49,192] @ [192,576]; each thread owns one output column per chunk ----
    const float4* x4p = (const float4*)xn;   // row stride 48 float4s
    #pragma unroll 1
    for (int chunk = 0; chunk < 3; chunk++) {
        int n = chunk*192 + tid;
        float acc[NTOK];
        float bn = qkv_b[n];
        #pragma unroll
        for (int m = 0; m < NTOK; m++) acc[m] = bn;
        const float* wp = qkv_w + n;
        float cw0 = wp[0], cw1 = wp[576], cw2 = wp[1152], cw3 = wp[1728];
        #pragma unroll 1
        for (int k4 = 0; k4 < 48; k4++) {
            float nw0=0.f, nw1=0.f, nw2=0.f, nw3=0.f;
            if (k4 < 47) {
                const float* q = wp + (k4+1)*4*576;
                nw0 = q[0]; nw1 = q[576]; nw2 = q[1152]; nw3 = q[1728];
            }
            #pragma unroll
            for (int m = 0; m < NTOK; m++) {
                float4 xv = x4p[m*48 + k4];
                acc[m] += xv.x*cw0 + xv.y*cw1 + xv.z*cw2 + xv.w*cw3;
            }
            cw0 = nw0; cw1 = nw1; cw2 = nw2; cw3 = nw3;
        }
        #pragma unroll
        for (int m = 0; m < NTOK; m++) qkv[m*576 + n] = acc[m];
    }
    __syncthreads();

    // ---- scores: s[h][i][j] stored transposed+padded at xn[h*2548 + j*52 + i] ----
    const float scale = 0.17677669529663687f; // 32^-0.5
    for (int idx = tid; idx < NHEAD*NTOK*NTOK; idx += 192) {
        int h = idx / 2401;
        int r = idx - h*2401;
        int i = r / 49;
        int j = r - i*49;
        const float4* qp = (const float4*)(qkv + i*576 + h*32);
        const float4* kp = (const float4*)(qkv + j*576 + 192 + h*32);
        float s = 0.f;
        #pragma unroll
        for (int t = 0; t < 8; t++) {
            float4 a = qp[t]; float4 c = kp[t];
            s += a.x*c.x + a.y*c.y + a.z*c.z + a.w*c.w;
        }
        xn[h*2548 + j*52 + i] = s * scale;
    }
    __syncthreads();

    // ---- softmax over j for each (h,i): 294 rows ----
    for (int r = tid; r < NHEAD*NTOK; r += 192) {
        int h = r / 49;
        int i = r - h*49;
        float* p = xn + h*2548 + i;
        float mx = -1e30f;
        for (int j = 0; j < NTOK; j++) mx = fmaxf(mx, p[j*52]);
        float s = 0.f;
        for (int j = 0; j < NTOK; j++) { float e = __expf(p[j*52] - mx); p[j*52] = e; s += e; }
        float inv = 1.f / s;
        for (int j = 0; j < NTOK; j++) p[j*52] *= inv;
    }
    __syncthreads();

    // ---- AV: out[i][c] = sum_j attn[h][i][j]*v[j][c]; out overwrites q slots ----
    {
        const int c = tid;
        const int h = c >> 5;
        const float* vbase = qkv + 384 + c;
        const float4* at = (const float4*)(xn + h*2548);
        float4 acc4[13];
        #pragma unroll
        for (int t = 0; t < 13; t++) acc4[t] = make_float4(0.f,0.f,0.f,0.f);
        #pragma unroll 1
        for (int j = 0; j < NTOK; j++) {
            float vj = vbase[j*576];
            const float4* aj = at + j*13;
            #pragma unroll
            for (int t = 0; t < 13; t++) {
                float4 a = aj[t];
                acc4[t].x += a.x*vj; acc4[t].y += a.y*vj;
                acc4[t].z += a.z*vj; acc4[t].w += a.w*vj;
            }
        }
        float* oc = qkv + c;
        const float* accs = (const float*)acc4;
        #pragma unroll
        for (int i = 0; i < NTOK; i++) oc[i*576] = accs[i];
    }
    __syncthreads();

    // ---- proj: y[m][n] = out[m][:] @ proj_w[:,n] + proj_b[n], n = tid ----
    {
        const int n = tid;
        float acc[NTOK];
        float bn = proj_b[n];
        #pragma unroll
        for (int m = 0; m < NTOK; m++) acc[m] = bn;
        const float* wp = proj_w + n;
        float cw0 = wp[0], cw1 = wp[192], cw2 = wp[384], cw3 = wp[576];
        #pragma unroll 1
        for (int c4 = 0; c4 < 48; c4++) {
            float nw0=0.f, nw1=0.f, nw2=0.f, nw3=0.f;
            if (c4 < 47) {
                const float* q = wp + (c4+1)*4*192;
                nw0 = q[0]; nw1 = q[192]; nw2 = q[384]; nw3 = q[576];
            }
            #pragma unroll
            for (int m = 0; m < NTOK; m++) {
                float4 ov = *((const float4*)(qkv + m*576) + c4);
                acc[m] += ov.x*cw0 + ov.y*cw1 + ov.z*cw2 + ov.w*cw3;
            }
            cw0 = nw0; cw1 = nw1; cw2 = nw2; cw3 = nw3;
        }
        // y into region A (scores are dead)
        #pragma unroll
        for (int m = 0; m < NTOK; m++) xn[m*CDIM + tid] = acc[m];
    }
    __syncthreads();

    // ---- LN2 stats on y ----
    if (tid < NTOK) {
        const float* r = xn + tid*CDIM;
        int off = (tid & 31) * 6;
        float s = 0.f, s2 = 0.f;
        for (int kk = 0; kk < CDIM; kk++) {
            int k = kk + off; if (k >= CDIM) k -= CDIM;
            float v = r[k]; s += v; s2 += v*v;
        }
        float m_ = s * (1.f/CDIM);
        float v_ = s2 * (1.f/CDIM) - m_*m_;
        mu[tid] = m_;
        rs[tid] = rsqrtf(v_ + 1e-5f);
    }
    __syncthreads();

    // ---- scatter with reverse shift; write x_attn and xn2 ----
    {
        float gc = g2[tid], bc = be2[tid];
        float* xa = g_xattn + (size_t)b * (HW*HW) * CDIM;
        float* x2 = g_xn2   + (size_t)b * (HW*HW) * CDIM;
        #pragma unroll 1
        for (int m = 0; m < NTOK; m++) {
            int ti = m / 7, tj = m - ti*7;
            int sr = wr*7 + ti + 3; if (sr >= HW) sr -= HW;
            int sc = wc*7 + tj + 3; if (sc >= HW) sc -= HW;
            float v = xn[m*CDIM + tid];
            size_t off = (size_t)(sr*HW + sc)*CDIM + tid;
            xa[off] = v;
            x2[off] = (v - mu[m]) * rs[m] * gc + bc;
        }
    }
}

// ---------------- tiled SGEMM body: 64x64 tile, BK=16, 256 thr, 4x4 microtile ----------------
template<int Nn, int Kk, int MODE>
__device__ __forceinline__ void gemm_body(const float* __restrict__ A,
                                          const float* __restrict__ Bw,
                                          const float* __restrict__ bias,
                                          const float* __restrict__ res,
                                          float* __restrict__ C)
{
    __shared__ float As[16][68];
    __shared__ float Bs[16][64];
    const int tid = threadIdx.x;
    const int tx = tid & 15, ty = tid >> 4;
    const int m0 = blockIdx.y * 64, n0 = blockIdx.x * 64;
    const int ar = tid >> 2, a4 = tid & 3;
    const int br = tid >> 4, bc = tid & 15;

    float acc[4][4] = {};

    for (int k0 = 0; k0 < Kk; k0 += 16) {
        float4 av = *(const float4*)(A + (size_t)(m0+ar)*Kk + k0 + a4*4);
        As[a4*4+0][ar] = av.x; As[a4*4+1][ar] = av.y;
        As[a4*4+2][ar] = av.z; As[a4*4+3][ar] = av.w;
        *(float4*)(&Bs[br][bc*4]) = *(const float4*)(Bw + (size_t)(k0+br)*Nn + n0 + bc*4);
        __syncthreads();
        #pragma unroll
        for (int k = 0; k < 16; k++) {
            float4 a  = *(const float4*)(&As[k][ty*4]);
            float4 bv = *(const float4*)(&Bs[k][tx*4]);
            acc[0][0] += a.x*bv.x; acc[0][1] += a.x*bv.y; acc[0][2] += a.x*bv.z; acc[0][3] += a.x*bv.w;
            acc[1][0] += a.y*bv.x; acc[1][1] += a.y*bv.y; acc[1][2] += a.y*bv.z; acc[1][3] += a.y*bv.w;
            acc[2][0] += a.z*bv.x; acc[2][1] += a.z*bv.y; acc[2][2] += a.z*bv.z; acc[2][3] += a.z*bv.w;
            acc[3][0] += a.w*bv.x; acc[3][1] += a.w*bv.y; acc[3][2] += a.w*bv.z; acc[3][3] += a.w*bv.w;
        }
        __syncthreads();
    }

    float4 bv = *(const float4*)(bias + n0 + tx*4);
    #pragma unroll
    for (int i = 0; i < 4; i++) {
        size_t row = (size_t)(m0 + ty*4 + i);
        float4 v;
        v.x = acc[i][0] + bv.x; v.y = acc[i][1] + bv.y;
        v.z = acc[i][2] + bv.z; v.w = acc[i][3] + bv.w;
        if (MODE == 0) {
            // exact GELU: 0.5*x*(1+erf(x/sqrt(2)))
            v.x = 0.5f*v.x*(1.f + erff(v.x*0.70710678118654752f));
            v.y = 0.5f*v.y*(1.f + erff(v.y*0.70710678118654752f));
            v.z = 0.5f*v.z*(1.f + erff(v.z*0.70710678118654752f));
            v.w = 0.5f*v.w*(1.f + erff(v.w*0.70710678118654752f));
        } else {
            float4 r = *(const float4*)(res + row*Nn + n0 + tx*4);
            v.x += r.x; v.y += r.y; v.z += r.z; v.w += r.w;
        }
        *(float4*)(C + row*Nn + n0 + tx*4) = v;
    }
}

__global__ void __launch_bounds__(256)
mlp1_kernel(const float* __restrict__ w1, const float* __restrict__ b1)
{
    gemm_body<HID, CDIM, 0>(g_xn2, w1, b1, nullptr, g_h);
}

__global__ void __launch_bounds__(256)
mlp2_kernel(const float* __restrict__ w2, const float* __restrict__ b2, float* __restrict__ out)
{
    gemm_body<CDIM, HID, 1>(g_h, w2, b2, g_xattn, out);
}

// ---------------- launch ----------------
extern "C" void kernel_launch(void* const* d_in, const int* in_sizes, int n_in,
                              void* d_out, int out_size)
{
    const float* x      = (const float*)d_in[0];
    const float* qkv_w  = (const float*)d_in[1];
    const float* qkv_b  = (const float*)d_in[2];
    const float* proj_w = (const float*)d_in[3];
    const float* proj_b = (const float*)d_in[4];
    const float* g1     = (const float*)d_in[5];
    const float* be1    = (const float*)d_in[6];
    const float* g2     = (const float*)d_in[7];
    const float* be2    = (const float*)d_in[8];
    const float* w1     = (const float*)d_in[9];
    const float* b1     = (const float*)d_in[10];
    const float* w2     = (const float*)d_in[11];
    const float* b2     = (const float*)d_in[12];
    float* out = (float*)d_out;

    (void)cudaFuncSetAttribute(attn_kernel, cudaFuncAttributeMaxDynamicSharedMemorySize, SMEM_BYTES);

    attn_kernel<<<BSZ*NWIN, 192, SMEM_BYTES>>>(x, qkv_w, qkv_b, proj_w, proj_b, g1, be1, g2, be2);
    mlp1_kernel<<<dim3(HID/64, TTOT/64), 256>>>(w1, b1);
    mlp2_kernel<<<dim3(CDIM/64, TTOT/64), 256>>>(w2, b2, out);
}

// round 3
// speedup vs baseline: 1.5667x; 1.5667x over previous
#include <cuda_runtime.h>
#include <math.h>

// ---------------- problem constants ----------------
#define BSZ   32
#define HW    56
#define CDIM  192
#define NHEAD 6
#define HD    32
#define NTOK  49
#define NWIN  64
#define TTOT  (BSZ*HW*HW)
#define HID   768
#define QST   580              // qkv row stride: 580 mod 32 = 4 -> conflict-free float4 strided access

// scratch (bss, no allocation)
__device__ float g_xattn[TTOT * CDIM];
__device__ float g_xn2  [TTOT * CDIM];
__device__ float g_h    [TTOT * HID];

// ---------------- attention smem layout (floats) ----------------
// region A: xn (49*192=9408) -> scores_t [6][49*52] (15288) -> y (9408)
#define QKV_OFF  15296
#define MU_OFF   (QKV_OFF + NTOK*QST)
#define RS_OFF   (MU_OFF + 56)
#define SMEM_FLOATS (RS_OFF + 56)
#define SMEM_BYTES  (SMEM_FLOATS * 4)

template<int T0, int TN>
__device__ __forceinline__ void av_part(float* qkv, const float* A, int c, int h)
{
    const float* vb = qkv + 384 + c;
    const float4* at = (const float4*)(A + h*2548);
    float4 acc4[TN];
    #pragma unroll
    for (int t = 0; t < TN; t++) acc4[t] = make_float4(0.f,0.f,0.f,0.f);
    #pragma unroll 1
    for (int j = 0; j < NTOK; j++) {
        float vj = vb[j*QST];
        const float4* aj = at + j*13 + T0;
        #pragma unroll
        for (int t = 0; t < TN; t++) {
            float4 a = aj[t];
            acc4[t].x += a.x*vj; acc4[t].y += a.y*vj;
            acc4[t].z += a.z*vj; acc4[t].w += a.w*vj;
        }
    }
    float* oc = qkv + c;
    const float* av = (const float*)acc4;
    #pragma unroll
    for (int u = 0; u < TN*4; u++) {
        int i = T0*4 + u;
        if (i < NTOK) oc[i*QST] = av[u];
    }
}

__global__ void __launch_bounds__(384)
attn_kernel(const float* __restrict__ x,
            const float* __restrict__ qkv_w, const float* __restrict__ qkv_b,
            const float* __restrict__ proj_w, const float* __restrict__ proj_b,
            const float* __restrict__ g1, const float* __restrict__ be1,
            const float* __restrict__ g2, const float* __restrict__ be2)
{
    extern __shared__ float sm[];
    float* A   = sm;              // xn -> scores -> y
    float* qkv = sm + QKV_OFF;
    float* mu  = sm + MU_OFF;
    float* rs  = sm + RS_OFF;

    const int tid  = threadIdx.x;
    const int grp  = tid >= 192 ? 1 : 0;
    const int col  = tid - grp*192;
    const int mlo  = grp ? 25 : 0;
    const int mhi  = grp ? 49 : 25;
    const int wid  = tid >> 5, lane = tid & 31;

    const int blk = blockIdx.x;
    const int b  = blk >> 6;
    const int w  = blk & 63;
    const int wr = w >> 3, wc = w & 7;

    const float* xb = x + (size_t)b * (HW*HW) * CDIM;

    // ---- gather shifted window ----
    #pragma unroll 1
    for (int m = mlo; m < mhi; m++) {
        int ti = m / 7, tj = m - ti*7;
        int sr = wr*7 + ti + 3; if (sr >= HW) sr -= HW;
        int sc = wc*7 + tj + 3; if (sc >= HW) sc -= HW;
        A[m*CDIM + col] = xb[(size_t)(sr*HW + sc)*CDIM + col];
    }
    __syncthreads();

    // ---- LN1 stats: warp per row ----
    for (int r = wid; r < NTOK; r += 12) {
        const float* p = A + r*CDIM + lane;
        float s = 0.f, s2 = 0.f;
        #pragma unroll
        for (int q = 0; q < 6; q++) { float v = p[q*32]; s += v; s2 += v*v; }
        #pragma unroll
        for (int o = 16; o; o >>= 1) { s += __shfl_xor_sync(~0u, s, o); s2 += __shfl_xor_sync(~0u, s2, o); }
        if (lane == 0) {
            float m_ = s * (1.f/CDIM);
            float v_ = s2 * (1.f/CDIM) - m_*m_;
            mu[r] = m_; rs[r] = rsqrtf(v_ + 1e-5f);
        }
    }
    __syncthreads();
    {
        float gc = g1[col], bc = be1[col];
        #pragma unroll 1
        for (int m = mlo; m < mhi; m++)
            A[m*CDIM + col] = (A[m*CDIM + col] - mu[m]) * rs[m] * gc + bc;
    }
    __syncthreads();

    const float4* x4 = (const float4*)A;

    // ---- QKV pass 1: q and k columns (n = tid, 0..383), all 49 rows ----
    {
        const int n = tid;
        float acc[NTOK];
        float bn = qkv_b[n];
        #pragma unroll
        for (int m = 0; m < NTOK; m++) acc[m] = bn;
        const float* wp = qkv_w + n;
        float c0 = wp[0], c1 = wp[576], c2 = wp[1152], c3 = wp[1728];
        #pragma unroll 1
        for (int k4 = 0; k4 < 48; k4++) {
            float n0=0.f,n1=0.f,n2=0.f,n3=0.f;
            if (k4 < 47) {
                const float* q = wp + (k4+1)*2304;
                n0 = q[0]; n1 = q[576]; n2 = q[1152]; n3 = q[1728];
            }
            #pragma unroll
            for (int m = 0; m < NTOK; m++) {
                float4 xv = x4[m*48 + k4];
                acc[m] += xv.x*c0 + xv.y*c1 + xv.z*c2 + xv.w*c3;
            }
            c0=n0; c1=n1; c2=n2; c3=n3;
        }
        #pragma unroll
        for (int m = 0; m < NTOK; m++) qkv[m*QST + n] = acc[m];
    }
    // ---- QKV pass 2: v columns (192), rows split 25/25 (row 24 duplicated, same value) ----
    {
        const int n = 384 + col;
        const int base = grp ? 24 : 0;
        float acc[25];
        float bn = qkv_b[n];
        #pragma unroll
        for (int u = 0; u < 25; u++) acc[u] = bn;
        const float* wp = qkv_w + n;
        float c0 = wp[0], c1 = wp[576], c2 = wp[1152], c3 = wp[1728];
        #pragma unroll 1
        for (int k4 = 0; k4 < 48; k4++) {
            float n0=0.f,n1=0.f,n2=0.f,n3=0.f;
            if (k4 < 47) {
                const float* q = wp + (k4+1)*2304;
                n0 = q[0]; n1 = q[576]; n2 = q[1152]; n3 = q[1728];
            }
            #pragma unroll
            for (int u = 0; u < 25; u++) {
                float4 xv = x4[(base+u)*48 + k4];
                acc[u] += xv.x*c0 + xv.y*c1 + xv.z*c2 + xv.w*c3;
            }
            c0=n0; c1=n1; c2=n2; c3=n3;
        }
        #pragma unroll
        for (int u = 0; u < 25; u++) qkv[(base+u)*QST + n] = acc[u];
    }
    __syncthreads();

    // ---- scores: s[h][i][j] -> A[h*2548 + j*52 + i] ----
    const float scale = 0.17677669529663687f;
    #pragma unroll 1
    for (int idx = tid; idx < NHEAD*NTOK*NTOK; idx += 384) {
        int h = idx / 2401;
        int r2 = idx - h*2401;
        int i = r2 / 49, j = r2 - i*49;
        const float4* qp = (const float4*)(qkv + i*QST + h*32);
        const float4* kp = (const float4*)(qkv + j*QST + 192 + h*32);
        float s = 0.f;
        #pragma unroll
        for (int t = 0; t < 8; t++) {
            float4 a = qp[t], c = kp[t];
            s += a.x*c.x + a.y*c.y + a.z*c.z + a.w*c.w;
        }
        A[h*2548 + j*52 + i] = s * scale;
    }
    __syncthreads();

    // ---- softmax over j, 294 rows ----
    if (tid < NHEAD*NTOK) {
        int h = tid / 49, i = tid - h*49;
        float* p = A + h*2548 + i;
        float mx = -1e30f;
        #pragma unroll 1
        for (int j = 0; j < NTOK; j++) mx = fmaxf(mx, p[j*52]);
        float s = 0.f;
        #pragma unroll 1
        for (int j = 0; j < NTOK; j++) { float e = __expf(p[j*52] - mx); p[j*52] = e; s += e; }
        float inv = 1.f / s;
        #pragma unroll 1
        for (int j = 0; j < NTOK; j++) p[j*52] *= inv;
    }
    __syncthreads();

    // ---- AV: out[i][c] = sum_j attn[h][i][j] * v[j][c]; out -> q slots ----
    {
        int c = col, h = c >> 5;
        if (!grp) av_part<0,7>(qkv, A, c, h);
        else      av_part<7,6>(qkv, A, c, h);
    }
    __syncthreads();

    // ---- proj: y[m][n], rows split 25/25 (row 24 duplicate, same value) ----
    {
        const int n = col;
        const int base = grp ? 24 : 0;
        float acc[25];
        float bn = proj_b[n];
        #pragma unroll
        for (int u = 0; u < 25; u++) acc[u] = bn;
        const float* wp = proj_w + n;
        float c0 = wp[0], c1 = wp[192], c2 = wp[384], c3 = wp[576];
        #pragma unroll 1
        for (int c4 = 0; c4 < 48; c4++) {
            float n0=0.f,n1=0.f,n2=0.f,n3=0.f;
            if (c4 < 47) {
                const float* q = wp + (c4+1)*768;
                n0 = q[0]; n1 = q[192]; n2 = q[384]; n3 = q[576];
            }
            #pragma unroll
            for (int u = 0; u < 25; u++) {
                float4 ov = *((const float4*)(qkv + (base+u)*QST) + c4);
                acc[u] += ov.x*c0 + ov.y*c1 + ov.z*c2 + ov.w*c3;
            }
            c0=n0; c1=n1; c2=n2; c3=n3;
        }
        #pragma unroll
        for (int u = 0; u < 25; u++) A[(base+u)*CDIM + n] = acc[u];
    }
    __syncthreads();

    // ---- LN2 stats ----
    for (int r = wid; r < NTOK; r += 12) {
        const float* p = A + r*CDIM + lane;
        float s = 0.f, s2 = 0.f;
        #pragma unroll
        for (int q = 0; q < 6; q++) { float v = p[q*32]; s += v; s2 += v*v; }
        #pragma unroll
        for (int o = 16; o; o >>= 1) { s += __shfl_xor_sync(~0u, s, o); s2 += __shfl_xor_sync(~0u, s2, o); }
        if (lane == 0) {
            float m_ = s * (1.f/CDIM);
            float v_ = s2 * (1.f/CDIM) - m_*m_;
            mu[r] = m_; rs[r] = rsqrtf(v_ + 1e-5f);
        }
    }
    __syncthreads();

    // ---- scatter with reverse shift; write x_attn and xn2 ----
    {
        float gc = g2[col], bc = be2[col];
        float* xa = g_xattn + (size_t)b * (HW*HW) * CDIM;
        float* x2 = g_xn2   + (size_t)b * (HW*HW) * CDIM;
        #pragma unroll 1
        for (int m = mlo; m < mhi; m++) {
            int ti = m / 7, tj = m - ti*7;
            int sr = wr*7 + ti + 3; if (sr >= HW) sr -= HW;
            int sc = wc*7 + tj + 3; if (sc >= HW) sc -= HW;
            float v = A[m*CDIM + col];
            size_t off = (size_t)(sr*HW + sc)*CDIM + col;
            xa[off] = v;
            x2[off] = (v - mu[m]) * rs[m] * gc + bc;
        }
    }
}

// ---------------- MLP1: [100352,192] @ [192,768] + gelu; 128x128x8 DB, 8x8 micro ----------------
__device__ __forceinline__ float gelu_exact(float v)
{
    return 0.5f * v * (1.f + erff(v * 0.70710678118654752f));
}

__global__ void __launch_bounds__(256)
mlp1_kernel(const float* __restrict__ w1, const float* __restrict__ b1)
{
    __shared__ float As[2][8][132];
    __shared__ float Bs[2][8][128];
    const float* Aa = g_xn2;
    const int K = CDIM, N = HID;
    const int tid = threadIdx.x;
    const int m0 = blockIdx.y * 128, n0 = blockIdx.x * 128;
    const int arow = tid >> 1, akc = (tid & 1) * 4;
    const int brow = tid >> 5, bcol = (tid & 31) * 4;
    const int ty = tid >> 4, tx = tid & 15;

    float acc[8][8] = {};

    float4 a0 = *(const float4*)(Aa + (size_t)(m0+arow)*K + akc);
    float4 bq = *(const float4*)(w1 + (size_t)brow*N + n0 + bcol);
    As[0][akc+0][arow] = a0.x; As[0][akc+1][arow] = a0.y;
    As[0][akc+2][arow] = a0.z; As[0][akc+3][arow] = a0.w;
    *(float4*)&Bs[0][brow][bcol] = bq;
    __syncthreads();

    int p = 0;
    for (int k0 = 8; k0 <= K; k0 += 8) {
        float4 an, bn;
        bool has = (k0 < K);
        if (has) {
            an = *(const float4*)(Aa + (size_t)(m0+arow)*K + k0 + akc);
            bn = *(const float4*)(w1 + (size_t)(k0+brow)*N + n0 + bcol);
        }
        #pragma unroll
        for (int k = 0; k < 8; k++) {
            float ar[8], br[8];
            *(float4*)(ar)   = *(const float4*)&As[p][k][ty*4];
            *(float4*)(ar+4) = *(const float4*)&As[p][k][64 + ty*4];
            *(float4*)(br)   = *(const float4*)&Bs[p][k][tx*4];
            *(float4*)(br+4) = *(const float4*)&Bs[p][k][64 + tx*4];
            #pragma unroll
            for (int i = 0; i < 8; i++)
                #pragma unroll
                for (int j = 0; j < 8; j++)
                    acc[i][j] += ar[i]*br[j];
        }
        if (has) {
            As[1-p][akc+0][arow] = an.x; As[1-p][akc+1][arow] = an.y;
            As[1-p][akc+2][arow] = an.z; As[1-p][akc+3][arow] = an.w;
            *(float4*)&Bs[1-p][brow][bcol] = bn;
        }
        __syncthreads();
        p ^= 1;
    }

    float4 bv0 = *(const float4*)(b1 + n0 + tx*4);
    float4 bv1 = *(const float4*)(b1 + n0 + 64 + tx*4);
    const float bb[8] = {bv0.x,bv0.y,bv0.z,bv0.w, bv1.x,bv1.y,bv1.z,bv1.w};
    #pragma unroll
    for (int i = 0; i < 8; i++) {
        int row = m0 + ((i < 4) ? (ty*4 + i) : (64 + ty*4 + i - 4));
        float4 v0, v1;
        v0.x = gelu_exact(acc[i][0]+bb[0]); v0.y = gelu_exact(acc[i][1]+bb[1]);
        v0.z = gelu_exact(acc[i][2]+bb[2]); v0.w = gelu_exact(acc[i][3]+bb[3]);
        v1.x = gelu_exact(acc[i][4]+bb[4]); v1.y = gelu_exact(acc[i][5]+bb[5]);
        v1.z = gelu_exact(acc[i][6]+bb[6]); v1.w = gelu_exact(acc[i][7]+bb[7]);
        *(float4*)(g_h + (size_t)row*N + n0 + tx*4)      = v0;
        *(float4*)(g_h + (size_t)row*N + n0 + 64 + tx*4) = v1;
    }
}

// ---------------- MLP2: [100352,768] @ [768,192] + bias + residual; 128x64x8 DB, 8x4 micro ----
__global__ void __launch_bounds__(256)
mlp2_kernel(const float* __restrict__ w2, const float* __restrict__ b2, float* __restrict__ out)
{
    __shared__ float As[2][8][132];
    __shared__ float Bs[2][8][64];
    const float* Aa = g_h;
    const int K = HID, N = CDIM;
    const int tid = threadIdx.x;
    const int m0 = blockIdx.y * 128, n0 = blockIdx.x * 64;
    const int arow = tid >> 1, akc = (tid & 1) * 4;
    const int brow = tid >> 5, bcol = (tid & 31) * 2;
    const int ty = tid >> 4, tx = tid & 15;

    float acc[8][4] = {};

    float4 a0 = *(const float4*)(Aa + (size_t)(m0+arow)*K + akc);
    float2 bq = *(const float2*)(w2 + (size_t)brow*N + n0 + bcol);
    As[0][akc+0][arow] = a0.x; As[0][akc+1][arow] = a0.y;
    As[0][akc+2][arow] = a0.z; As[0][akc+3][arow] = a0.w;
    *(float2*)&Bs[0][brow][bcol] = bq;
    __syncthreads();

    int p = 0;
    for (int k0 = 8; k0 <= K; k0 += 8) {
        float4 an; float2 bn;
        bool has = (k0 < K);
        if (has) {
            an = *(const float4*)(Aa + (size_t)(m0+arow)*K + k0 + akc);
            bn = *(const float2*)(w2 + (size_t)(k0+brow)*N + n0 + bcol);
        }
        #pragma unroll
        for (int k = 0; k < 8; k++) {
            float ar[8], br[4];
            *(float4*)(ar)   = *(const float4*)&As[p][k][ty*4];
            *(float4*)(ar+4) = *(const float4*)&As[p][k][64 + ty*4];
            *(float4*)(br)   = *(const float4*)&Bs[p][k][tx*4];
            #pragma unroll
            for (int i = 0; i < 8; i++)
                #pragma unroll
                for (int j = 0; j < 4; j++)
                    acc[i][j] += ar[i]*br[j];
        }
        if (has) {
            As[1-p][akc+0][arow] = an.x; As[1-p][akc+1][arow] = an.y;
            As[1-p][akc+2][arow] = an.z; As[1-p][akc+3][arow] = an.w;
            *(float2*)&Bs[1-p][brow][bcol] = bn;
        }
        __syncthreads();
        p ^= 1;
    }

    float4 bv = *(const float4*)(b2 + n0 + tx*4);
    #pragma unroll
    for (int i = 0; i < 8; i++) {
        int row = m0 + ((i < 4) ? (ty*4 + i) : (64 + ty*4 + i - 4));
        float4 r = *(const float4*)(g_xattn + (size_t)row*N + n0 + tx*4);
        float4 v;
        v.x = acc[i][0] + bv.x + r.x;
        v.y = acc[i][1] + bv.y + r.y;
        v.z = acc[i][2] + bv.z + r.z;
        v.w = acc[i][3] + bv.w + r.w;
        *(float4*)(out + (size_t)row*N + n0 + tx*4) = v;
    }
}

// ---------------- launch ----------------
extern "C" void kernel_launch(void* const* d_in, const int* in_sizes, int n_in,
                              void* d_out, int out_size)
{
    const float* x      = (const float*)d_in[0];
    const float* qkv_w  = (const float*)d_in[1];
    const float* qkv_b  = (const float*)d_in[2];
    const float* proj_w = (const float*)d_in[3];
    const float* proj_b = (const float*)d_in[4];
    const float* g1     = (const float*)d_in[5];
    const float* be1    = (const float*)d_in[6];
    const float* g2     = (const float*)d_in[7];
    const float* be2    = (const float*)d_in[8];
    const float* w1     = (const float*)d_in[9];
    const float* b1     = (const float*)d_in[10];
    const float* w2     = (const float*)d_in[11];
    const float* b2     = (const float*)d_in[12];
    float* out = (float*)d_out;

    (void)cudaFuncSetAttribute(attn_kernel, cudaFuncAttributeMaxDynamicSharedMemorySize, SMEM_BYTES);

    attn_kernel<<<BSZ*NWIN, 384, SMEM_BYTES>>>(x, qkv_w, qkv_b, proj_w, proj_b, g1, be1, g2, be2);
    mlp1_kernel<<<dim3(HID/128, TTOT/128), 256>>>(w1, b1);
    mlp2_kernel<<<dim3(CDIM/64, TTOT/128), 256>>>(w2, b2, out);
}